// round 1
// baseline (speedup 1.0000x reference)
#include <cuda_runtime.h>
#include <math.h>

// Problem constants
constexpr int B_ = 64;
constexpr int N_ = 1024;
constexpr int D_ = 512;
constexpr int K_ = 64;
constexpr int C_ = K_ + N_;          // 1088
constexpr long OUT_ELEMS = (long)B_ * K_ * D_;   // 2,097,152
constexpr long DOTS_OFF  = OUT_ELEMS;            // dots follows out in d_out

#define TEMP_INV (1.0f / 0.07f)

// Scratch (device globals — no allocation allowed in kernel_launch)
__device__ float g_shat[K_ * D_];        // normalized slot embeddings
__device__ float g_S[K_ * K_];           // slot-slot cosine sims
__device__ float g_kinv[B_ * N_];        // 1/||key row||
__device__ float g_attn[(long)B_ * K_ * C_];   // normalized attention weights (17.8 MB)

// ---------------------------------------------------------------------------
// K1: normalize slot embeddings. One block per slot, 128 threads.
// ---------------------------------------------------------------------------
__global__ void k_slot_norm(const float* __restrict__ slot) {
    int i = blockIdx.x;
    int t = threadIdx.x;
    float v[4];
    float ss = 0.f;
#pragma unroll
    for (int j = 0; j < 4; j++) {
        v[j] = slot[i * D_ + t + j * 128];
        ss += v[j] * v[j];
    }
#pragma unroll
    for (int o = 16; o; o >>= 1) ss += __shfl_xor_sync(0xffffffffu, ss, o);
    __shared__ float red[4];
    if ((t & 31) == 0) red[t >> 5] = ss;
    __syncthreads();
    float tot = red[0] + red[1] + red[2] + red[3];
    float inv = 1.f / fmaxf(sqrtf(tot), 1e-12f);
#pragma unroll
    for (int j = 0; j < 4; j++) g_shat[i * D_ + t + j * 128] = v[j] * inv;
}

// ---------------------------------------------------------------------------
// K2: S = Shat @ Shat^T  (tiny). Grid 64, block 64.
// ---------------------------------------------------------------------------
__global__ void k_slot_S() {
    int i = blockIdx.x, j = threadIdx.x;
    const float4* a = (const float4*)(g_shat + i * D_);
    const float4* b = (const float4*)(g_shat + j * D_);
    float acc = 0.f;
#pragma unroll 8
    for (int d = 0; d < D_ / 4; d++) {
        float4 x = a[d], y = b[d];
        acc += x.x * y.x + x.y * y.y + x.z * y.z + x.w * y.w;
    }
    g_S[i * K_ + j] = acc;
}

// ---------------------------------------------------------------------------
// K3: per-key-row inverse norms. One warp per row.
// ---------------------------------------------------------------------------
__global__ void k_key_norm(const float* __restrict__ key) {
    int warp = (blockIdx.x * blockDim.x + threadIdx.x) >> 5;
    int lane = threadIdx.x & 31;
    const float4* row = (const float4*)(key + (long)warp * D_);
    float ss = 0.f;
#pragma unroll
    for (int j = 0; j < 4; j++) {
        float4 v = row[lane + j * 32];
        ss += v.x * v.x + v.y * v.y + v.z * v.z + v.w * v.w;
    }
#pragma unroll
    for (int o = 16; o; o >>= 1) ss += __shfl_xor_sync(0xffffffffu, ss, o);
    if (lane == 0) g_kinv[warp] = 1.f / fmaxf(sqrtf(ss), 1e-12f);
}

// ---------------------------------------------------------------------------
// K4: dots_key[b, i, n] = (Shat_i . key[b,n]) * kinv[b,n]   -> dots output.
// Block tile: 64 slots x 128 keys, k-chunk 32. 256 threads, 8x4 micro-tile.
// ---------------------------------------------------------------------------
__global__ __launch_bounds__(256) void k_dots(const float* __restrict__ key,
                                              float* __restrict__ dout) {
    __shared__ float As[32][64];    // [kk][slot]
    __shared__ float Bs[32][128];   // [kk][key]
    int b  = blockIdx.y;
    int n0 = blockIdx.x * 128;
    int t  = threadIdx.x;
    int tx = t & 31;   // key micro: tx*4 .. tx*4+3
    int ty = t >> 5;   // slot micro: ty*8 .. ty*8+7
    float acc[8][4] = {};
    const float* keyb = key + (long)b * N_ * D_;

    for (int d0 = 0; d0 < D_; d0 += 32) {
        // stage A (Shat): 512 float4 loads, 2 per thread
#pragma unroll
        for (int r = 0; r < 2; r++) {
            int idx = t + r * 256;
            int slot = idx >> 3, f4 = idx & 7;
            float4 v = *(const float4*)(g_shat + slot * D_ + d0 + f4 * 4);
            As[f4 * 4 + 0][slot] = v.x;
            As[f4 * 4 + 1][slot] = v.y;
            As[f4 * 4 + 2][slot] = v.z;
            As[f4 * 4 + 3][slot] = v.w;
        }
        // stage B (key tile): 1024 float4 loads, 4 per thread
#pragma unroll
        for (int r = 0; r < 4; r++) {
            int idx = t + r * 256;
            int ki = idx >> 3, f4 = idx & 7;
            float4 v = *(const float4*)(keyb + (long)(n0 + ki) * D_ + d0 + f4 * 4);
            Bs[f4 * 4 + 0][ki] = v.x;
            Bs[f4 * 4 + 1][ki] = v.y;
            Bs[f4 * 4 + 2][ki] = v.z;
            Bs[f4 * 4 + 3][ki] = v.w;
        }
        __syncthreads();
#pragma unroll
        for (int kk = 0; kk < 32; kk++) {
            float4 a0 = *(const float4*)(&As[kk][ty * 8]);
            float4 a1 = *(const float4*)(&As[kk][ty * 8 + 4]);
            float4 b0 = *(const float4*)(&Bs[kk][tx * 4]);
            float a[8] = {a0.x, a0.y, a0.z, a0.w, a1.x, a1.y, a1.z, a1.w};
            float bb[4] = {b0.x, b0.y, b0.z, b0.w};
#pragma unroll
            for (int i = 0; i < 8; i++)
#pragma unroll
                for (int j = 0; j < 4; j++) acc[i][j] += a[i] * bb[j];
        }
        __syncthreads();
    }

    // epilogue: scale by key inverse norm, write dots key-part
    float kv[4];
#pragma unroll
    for (int j = 0; j < 4; j++) kv[j] = g_kinv[b * N_ + n0 + tx * 4 + j];
    float* dots = dout + DOTS_OFF + (long)b * K_ * C_;
#pragma unroll
    for (int i = 0; i < 8; i++) {
        int s = ty * 8 + i;
        float4 w = {acc[i][0] * kv[0], acc[i][1] * kv[1],
                    acc[i][2] * kv[2], acc[i][3] * kv[3]};
        *(float4*)(dots + (long)s * C_ + K_ + n0 + tx * 4) = w;
    }
}

// ---------------------------------------------------------------------------
// K5: per-(b,i) row softmax with block-causal mask; writes normalized attn
// weights to g_attn and the raw slot-slot dots into the dots output.
// One warp per row.
// ---------------------------------------------------------------------------
__global__ __launch_bounds__(256) void k_softmax(float* __restrict__ dout) {
    int row  = (blockIdx.x * blockDim.x + threadIdx.x) >> 5;   // 0..4095
    int lane = threadIdx.x & 31;
    int b = row >> 6, i = row & 63;

    float* drow = dout + DOTS_OFF + (long)b * K_ * C_ + (long)i * C_;

    float sv[2];          // slot-part values
    float kvv[32];        // key-part values
    float m = -1e30f;
#pragma unroll
    for (int r = 0; r < 2; r++) {
        int c = lane + r * 32;
        float s = g_S[i * K_ + c];
        sv[r] = s;
        drow[c] = s;                       // dots slot-part output (unmasked)
        if (c < i) m = fmaxf(m, s);        // mask: slot c allowed iff c < i
    }
#pragma unroll
    for (int r = 0; r < 32; r++) {
        float v = drow[K_ + lane + r * 32];
        kvv[r] = v;
        m = fmaxf(m, v);
    }
#pragma unroll
    for (int o = 16; o; o >>= 1) m = fmaxf(m, __shfl_xor_sync(0xffffffffu, m, o));

    float sum = 0.f;
    float es[2], ek[32];
#pragma unroll
    for (int r = 0; r < 2; r++) {
        int c = lane + r * 32;
        float x = (c < i) ? __expf((sv[r] - m) * TEMP_INV) : 0.f;
        es[r] = x; sum += x;
    }
#pragma unroll
    for (int r = 0; r < 32; r++) {
        float x = __expf((kvv[r] - m) * TEMP_INV);
        ek[r] = x; sum += x;
    }
#pragma unroll
    for (int o = 16; o; o >>= 1) sum += __shfl_xor_sync(0xffffffffu, sum, o);

    float inv = 1.f / (sum * (1.f + 1e-7f));
    float* at = g_attn + (long)row * C_;
#pragma unroll
    for (int r = 0; r < 2; r++) at[lane + r * 32] = es[r] * inv;
#pragma unroll
    for (int r = 0; r < 32; r++) at[K_ + lane + r * 32] = ek[r] * inv;
}

// ---------------------------------------------------------------------------
// K6: out[b, i, :] = attn_n[b, i, :] @ [slot_embed; key_b]   (1088 x 512)
// Block tile: 64 slots x 128 d-cols, k-chunk 32 over C=1088 (34 chunks).
// ---------------------------------------------------------------------------
__global__ __launch_bounds__(256) void k_out(const float* __restrict__ slot,
                                             const float* __restrict__ key,
                                             float* __restrict__ dout) {
    __shared__ float Ws[32][64];    // [kk][slot]
    __shared__ float Vs[32][128];   // [kk][dcol]
    int b  = blockIdx.y;
    int d0 = blockIdx.x * 128;
    int t  = threadIdx.x;
    int tx = t & 31;   // dcol micro: tx*4..+3
    int ty = t >> 5;   // slot micro: ty*8..+7
    float acc[8][4] = {};
    const float* attn = g_attn + (long)b * K_ * C_;
    const float* keyb = key + (long)b * N_ * D_;

    for (int c0 = 0; c0 < C_; c0 += 32) {
        // stage attn weights
#pragma unroll
        for (int r = 0; r < 2; r++) {
            int idx = t + r * 256;
            int s = idx >> 3, f4 = idx & 7;
            float4 v = *(const float4*)(attn + (long)s * C_ + c0 + f4 * 4);
            Ws[f4 * 4 + 0][s] = v.x;
            Ws[f4 * 4 + 1][s] = v.y;
            Ws[f4 * 4 + 2][s] = v.z;
            Ws[f4 * 4 + 3][s] = v.w;
        }
        // stage slot_key rows (slots for c<K, keys otherwise)
#pragma unroll
        for (int r = 0; r < 4; r++) {
            int idx = t + r * 256;
            int kk = idx >> 5, f4c = idx & 31;
            int c = c0 + kk;
            const float* src = (c < K_) ? (slot + (long)c * D_ + d0 + f4c * 4)
                                        : (keyb + (long)(c - K_) * D_ + d0 + f4c * 4);
            *(float4*)(&Vs[kk][f4c * 4]) = *(const float4*)src;
        }
        __syncthreads();
#pragma unroll
        for (int kk = 0; kk < 32; kk++) {
            float4 a0 = *(const float4*)(&Ws[kk][ty * 8]);
            float4 a1 = *(const float4*)(&Ws[kk][ty * 8 + 4]);
            float4 b0 = *(const float4*)(&Vs[kk][tx * 4]);
            float a[8] = {a0.x, a0.y, a0.z, a0.w, a1.x, a1.y, a1.z, a1.w};
            float bb[4] = {b0.x, b0.y, b0.z, b0.w};
#pragma unroll
            for (int i = 0; i < 8; i++)
#pragma unroll
                for (int j = 0; j < 4; j++) acc[i][j] += a[i] * bb[j];
        }
        __syncthreads();
    }

#pragma unroll
    for (int i = 0; i < 8; i++) {
        int s = ty * 8 + i;
        float4 w = {acc[i][0], acc[i][1], acc[i][2], acc[i][3]};
        *(float4*)(dout + (long)b * K_ * D_ + (long)s * D_ + d0 + tx * 4) = w;
    }
}

// ---------------------------------------------------------------------------
extern "C" void kernel_launch(void* const* d_in, const int* in_sizes, int n_in,
                              void* d_out, int out_size) {
    const float* key  = (const float*)d_in[0];   // [64, 1024, 512]
    const float* slot = (const float*)d_in[1];   // [64, 512]
    float* out = (float*)d_out;                  // [out | dots] fp32

    k_slot_norm<<<K_, 128>>>(slot);
    k_slot_S<<<K_, K_>>>();
    k_key_norm<<<(B_ * N_) / 8, 256>>>(key);
    k_dots<<<dim3(N_ / 128, B_), 256>>>(key, out);
    k_softmax<<<(B_ * K_) / 8, 256>>>(out);
    k_out<<<dim3(D_ / 128, B_), 256>>>(slot, key, out);
}

// round 2
// speedup vs baseline: 1.1807x; 1.1807x over previous
#include <cuda_runtime.h>
#include <math.h>

constexpr int B_ = 64;
constexpr int N_ = 1024;
constexpr int D_ = 512;
constexpr int K_ = 64;
constexpr int C_ = K_ + N_;                      // 1088
constexpr long OUT_ELEMS = (long)B_ * K_ * D_;
constexpr long DOTS_OFF  = OUT_ELEMS;

#define TEMP_INV (1.0f / 0.07f)

typedef unsigned long long ull;

__device__ float g_shat[K_ * D_];
__device__ float g_S[K_ * K_];
__device__ float g_kinv[B_ * N_];
__device__ float g_attn[(long)B_ * K_ * C_];

// ---- f32x2 packed helpers -------------------------------------------------
__device__ __forceinline__ ull fma2(ull a, ull b, ull c) {
    ull d;
    asm("fma.rn.f32x2 %0, %1, %2, %3;" : "=l"(d) : "l"(a), "l"(b), "l"(c));
    return d;
}
__device__ __forceinline__ ull dup2(float x) {
    ull d; unsigned r = __float_as_uint(x);
    asm("mov.b64 %0, {%1, %1};" : "=l"(d) : "r"(r));
    return d;
}
__device__ __forceinline__ void up2(ull u, float& lo, float& hi) {
    unsigned a, b;
    asm("mov.b64 {%0, %1}, %2;" : "=r"(a), "=r"(b) : "l"(u));
    lo = __uint_as_float(a); hi = __uint_as_float(b);
}

// ---------------------------------------------------------------------------
// K1: normalize slot embeddings
// ---------------------------------------------------------------------------
__global__ void k_slot_norm(const float* __restrict__ slot) {
    int i = blockIdx.x, t = threadIdx.x;
    float v[4]; float ss = 0.f;
#pragma unroll
    for (int j = 0; j < 4; j++) { v[j] = slot[i * D_ + t + j * 128]; ss += v[j] * v[j]; }
#pragma unroll
    for (int o = 16; o; o >>= 1) ss += __shfl_xor_sync(0xffffffffu, ss, o);
    __shared__ float red[4];
    if ((t & 31) == 0) red[t >> 5] = ss;
    __syncthreads();
    float inv = 1.f / fmaxf(sqrtf(red[0] + red[1] + red[2] + red[3]), 1e-12f);
#pragma unroll
    for (int j = 0; j < 4; j++) g_shat[i * D_ + t + j * 128] = v[j] * inv;
}

// ---------------------------------------------------------------------------
// K2: S = Shat @ Shat^T
// ---------------------------------------------------------------------------
__global__ void k_slot_S() {
    int i = blockIdx.x, j = threadIdx.x;
    const float4* a = (const float4*)(g_shat + i * D_);
    const float4* b = (const float4*)(g_shat + j * D_);
    float acc = 0.f;
#pragma unroll 8
    for (int d = 0; d < D_ / 4; d++) {
        float4 x = a[d], y = b[d];
        acc += x.x * y.x + x.y * y.y + x.z * y.z + x.w * y.w;
    }
    g_S[i * K_ + j] = acc;
}

// ---------------------------------------------------------------------------
// K3: per-key-row inverse norms
// ---------------------------------------------------------------------------
__global__ void k_key_norm(const float* __restrict__ key) {
    int warp = (blockIdx.x * blockDim.x + threadIdx.x) >> 5;
    int lane = threadIdx.x & 31;
    const float4* row = (const float4*)(key + (long)warp * D_);
    float ss = 0.f;
#pragma unroll
    for (int j = 0; j < 4; j++) {
        float4 v = row[lane + j * 32];
        ss += v.x * v.x + v.y * v.y + v.z * v.z + v.w * v.w;
    }
#pragma unroll
    for (int o = 16; o; o >>= 1) ss += __shfl_xor_sync(0xffffffffu, ss, o);
    if (lane == 0) g_kinv[warp] = 1.f / fmaxf(sqrtf(ss), 1e-12f);
}

// ---------------------------------------------------------------------------
// K4: dots key-part via f32x2 GEMM. Tile 64 slots x 256 keys, chunk 16.
// 256 threads, 8x8 micro (acc as 8x4 f32x2 over key pairs). Double-buffered.
// ---------------------------------------------------------------------------
__global__ __launch_bounds__(256, 2) void k_dots(const float* __restrict__ key,
                                                 float* __restrict__ dout) {
    __shared__ float As[2][16][68];
    __shared__ float Bs[2][16][260];
    const int b  = blockIdx.y;
    const int n0 = blockIdx.x * 256;
    const int t  = threadIdx.x;
    const int tx = t & 31;     // key cols: tx*4 + {0..3}, 128 + tx*4 + {0..3}
    const int ty = t >> 5;     // slots:    ty*4 + {0..3}, 32  + ty*4 + {0..3}
    const float* keyb = key + (long)b * N_ * D_;

    ull acc[8][4] = {};

    // staging indices
    const int a_slot = t >> 2, a_r = t & 3;          // A transpose
    const int b_f = t & 3,     b_rb = t >> 2;        // B transpose

    auto stage = [&](int d0, int bi) {
        // A: Shat[64 x 16] -> As[kk][slot]
        float4 va = *(const float4*)(g_shat + a_slot * D_ + d0 + a_r * 4);
        As[bi][a_r * 4 + 0][a_slot] = va.x;
        As[bi][a_r * 4 + 1][a_slot] = va.y;
        As[bi][a_r * 4 + 2][a_slot] = va.z;
        As[bi][a_r * 4 + 3][a_slot] = va.w;
        // B: key[256 x 16] -> Bs[kk][n] (transpose)
#pragma unroll
        for (int p = 0; p < 4; p++) {
            int n = b_rb + 64 * p;
            float4 v = *(const float4*)(keyb + (long)(n0 + n) * D_ + d0 + b_f * 4);
            Bs[bi][b_f * 4 + 0][n] = v.x;
            Bs[bi][b_f * 4 + 1][n] = v.y;
            Bs[bi][b_f * 4 + 2][n] = v.z;
            Bs[bi][b_f * 4 + 3][n] = v.w;
        }
    };

    stage(0, 0);
    __syncthreads();

    for (int it = 0; it < 32; it++) {
        int cur = it & 1;
        if (it < 31) stage((it + 1) * 16, cur ^ 1);
#pragma unroll
        for (int kk = 0; kk < 16; kk++) {
            float4 a0 = *(const float4*)&As[cur][kk][ty * 4];
            float4 a1 = *(const float4*)&As[cur][kk][32 + ty * 4];
            ulonglong2 b0 = *(const ulonglong2*)&Bs[cur][kk][tx * 4];
            ulonglong2 b1 = *(const ulonglong2*)&Bs[cur][kk][128 + tx * 4];
            ull aa[8] = {dup2(a0.x), dup2(a0.y), dup2(a0.z), dup2(a0.w),
                         dup2(a1.x), dup2(a1.y), dup2(a1.z), dup2(a1.w)};
            ull bb[4] = {b0.x, b0.y, b1.x, b1.y};
#pragma unroll
            for (int i = 0; i < 8; i++)
#pragma unroll
                for (int j = 0; j < 4; j++) acc[i][j] = fma2(aa[i], bb[j], acc[i][j]);
        }
        __syncthreads();
    }

    // epilogue: scale by key inverse norms, write dots key-part
    float* dots = dout + DOTS_OFF + (long)b * K_ * C_;
#pragma unroll
    for (int g = 0; g < 2; g++) {
        int n = n0 + tx * 4 + 128 * g;
        float4 kv = *(const float4*)(g_kinv + b * N_ + n);
#pragma unroll
        for (int i = 0; i < 8; i++) {
            int si = (i < 4) ? (ty * 4 + i) : (32 + ty * 4 + i - 4);
            float l0, h0, l1, h1;
            up2(acc[i][2 * g + 0], l0, h0);
            up2(acc[i][2 * g + 1], l1, h1);
            float4 w = {l0 * kv.x, h0 * kv.y, l1 * kv.z, h1 * kv.w};
            *(float4*)(dots + (long)si * C_ + K_ + n) = w;
        }
    }
}

// ---------------------------------------------------------------------------
// K5: row softmax with block-causal mask -> g_attn; slot-slot dots -> output.
// ---------------------------------------------------------------------------
__global__ __launch_bounds__(256) void k_softmax(float* __restrict__ dout) {
    int row  = (blockIdx.x * blockDim.x + threadIdx.x) >> 5;
    int lane = threadIdx.x & 31;
    int b = row >> 6, i = row & 63;

    float* drow = dout + DOTS_OFF + (long)b * K_ * C_ + (long)i * C_;

    float sv[2], kvv[32];
    float m = -1e30f;
#pragma unroll
    for (int r = 0; r < 2; r++) {
        int c = lane + r * 32;
        float s = g_S[i * K_ + c];
        sv[r] = s;
        drow[c] = s;
        if (c < i) m = fmaxf(m, s);
    }
#pragma unroll
    for (int r = 0; r < 32; r++) {
        float v = drow[K_ + lane + r * 32];
        kvv[r] = v;
        m = fmaxf(m, v);
    }
#pragma unroll
    for (int o = 16; o; o >>= 1) m = fmaxf(m, __shfl_xor_sync(0xffffffffu, m, o));

    float sum = 0.f, es[2], ek[32];
#pragma unroll
    for (int r = 0; r < 2; r++) {
        int c = lane + r * 32;
        float x = (c < i) ? __expf((sv[r] - m) * TEMP_INV) : 0.f;
        es[r] = x; sum += x;
    }
#pragma unroll
    for (int r = 0; r < 32; r++) {
        float x = __expf((kvv[r] - m) * TEMP_INV);
        ek[r] = x; sum += x;
    }
#pragma unroll
    for (int o = 16; o; o >>= 1) sum += __shfl_xor_sync(0xffffffffu, sum, o);

    float inv = 1.f / (sum * (1.f + 1e-7f));
    float* at = g_attn + (long)row * C_;
#pragma unroll
    for (int r = 0; r < 2; r++) at[lane + r * 32] = es[r] * inv;
#pragma unroll
    for (int r = 0; r < 32; r++) at[K_ + lane + r * 32] = ek[r] * inv;
}

// ---------------------------------------------------------------------------
// K6: out = attn_n @ [slots; key_b] via f32x2 GEMM. Tile 64 slots x 256 dcols,
// chunk 16 over C=1088 (68 iters). Same micro structure as k_dots.
// ---------------------------------------------------------------------------
__global__ __launch_bounds__(256, 2) void k_out(const float* __restrict__ slot,
                                                const float* __restrict__ key,
                                                float* __restrict__ dout) {
    __shared__ float Ws[2][16][68];
    __shared__ float Vs[2][16][260];
    const int b  = blockIdx.y;
    const int d0 = blockIdx.x * 256;
    const int t  = threadIdx.x;
    const int tx = t & 31;
    const int ty = t >> 5;
    const float* keyb  = key + (long)b * N_ * D_;
    const float* attnb = g_attn + (long)b * K_ * C_;

    ull acc[8][4] = {};

    const int w_slot = t >> 2, w_r = t & 3;   // W transpose staging
    const int v_kk = t >> 4,   v_f = t & 15;  // V direct staging

    auto stage = [&](int c0, int bi) {
        // W: attn[64 x 16] -> Ws[kk][slot]
        float4 vw = *(const float4*)(attnb + (long)w_slot * C_ + c0 + w_r * 4);
        Ws[bi][w_r * 4 + 0][w_slot] = vw.x;
        Ws[bi][w_r * 4 + 1][w_slot] = vw.y;
        Ws[bi][w_r * 4 + 2][w_slot] = vw.z;
        Ws[bi][w_r * 4 + 3][w_slot] = vw.w;
        // V: slot_key rows c0..c0+15, dcols d0..d0+255 (no transpose)
        int c = c0 + v_kk;
        const float* src = (c < K_) ? (slot + (long)c * D_ + d0)
                                    : (keyb + (long)(c - K_) * D_ + d0);
#pragma unroll
        for (int q = 0; q < 4; q++) {
            int f4 = v_f + 16 * q;
            *(float4*)&Vs[bi][v_kk][f4 * 4] = *(const float4*)(src + f4 * 4);
        }
    };

    stage(0, 0);
    __syncthreads();

    for (int it = 0; it < 68; it++) {
        int cur = it & 1;
        if (it < 67) stage((it + 1) * 16, cur ^ 1);
#pragma unroll
        for (int kk = 0; kk < 16; kk++) {
            float4 a0 = *(const float4*)&Ws[cur][kk][ty * 4];
            float4 a1 = *(const float4*)&Ws[cur][kk][32 + ty * 4];
            ulonglong2 b0 = *(const ulonglong2*)&Vs[cur][kk][tx * 4];
            ulonglong2 b1 = *(const ulonglong2*)&Vs[cur][kk][128 + tx * 4];
            ull aa[8] = {dup2(a0.x), dup2(a0.y), dup2(a0.z), dup2(a0.w),
                         dup2(a1.x), dup2(a1.y), dup2(a1.z), dup2(a1.w)};
            ull bb[4] = {b0.x, b0.y, b1.x, b1.y};
#pragma unroll
            for (int i = 0; i < 8; i++)
#pragma unroll
                for (int j = 0; j < 4; j++) acc[i][j] = fma2(aa[i], bb[j], acc[i][j]);
        }
        __syncthreads();
    }

#pragma unroll
    for (int g = 0; g < 2; g++) {
        int d = d0 + tx * 4 + 128 * g;
#pragma unroll
        for (int i = 0; i < 8; i++) {
            int si = (i < 4) ? (ty * 4 + i) : (32 + ty * 4 + i - 4);
            float l0, h0, l1, h1;
            up2(acc[i][2 * g + 0], l0, h0);
            up2(acc[i][2 * g + 1], l1, h1);
            float4 w = {l0, h0, l1, h1};
            *(float4*)(dout + (long)b * K_ * D_ + (long)si * D_ + d) = w;
        }
    }
}

// ---------------------------------------------------------------------------
extern "C" void kernel_launch(void* const* d_in, const int* in_sizes, int n_in,
                              void* d_out, int out_size) {
    const float* key  = (const float*)d_in[0];
    const float* slot = (const float*)d_in[1];
    float* out = (float*)d_out;

    k_slot_norm<<<K_, 128>>>(slot);
    k_slot_S<<<K_, K_>>>();
    k_key_norm<<<(B_ * N_) / 8, 256>>>(key);
    k_dots<<<dim3(N_ / 256, B_), 256>>>(key, out);
    k_softmax<<<(B_ * K_) / 8, 256>>>(out);
    k_out<<<dim3(D_ / 256, B_), 256>>>(slot, key, out);
}

// round 4
// speedup vs baseline: 1.4537x; 1.2312x over previous
#include <cuda_runtime.h>
#include <mma.h>
#include <cstdint>
#include <math.h>

using namespace nvcuda;

constexpr int B_ = 64;
constexpr int N_ = 1024;
constexpr int D_ = 512;
constexpr int K_ = 64;
constexpr int C_ = K_ + N_;                      // 1088
constexpr long OUT_ELEMS = (long)B_ * K_ * D_;
constexpr long DOTS_OFF  = OUT_ELEMS;

#define TEMP_INV (1.0f / 0.07f)

__device__ float g_shat[K_ * D_];
__device__ float g_S[K_ * K_];
__device__ float g_attn[(long)B_ * K_ * C_];

__device__ __forceinline__ float to_tf32(float x) {
    asm("cvt.rna.tf32.f32 %0, %1;" : "=f"(x) : "f"(x));
    return x;
}

// ---------------------------------------------------------------------------
// K1: normalize slot embeddings
// ---------------------------------------------------------------------------
__global__ void k_slot_norm(const float* __restrict__ slot) {
    int i = blockIdx.x, t = threadIdx.x;
    float v[4]; float ss = 0.f;
#pragma unroll
    for (int j = 0; j < 4; j++) { v[j] = slot[i * D_ + t + j * 128]; ss += v[j] * v[j]; }
#pragma unroll
    for (int o = 16; o; o >>= 1) ss += __shfl_xor_sync(0xffffffffu, ss, o);
    __shared__ float red[4];
    if ((t & 31) == 0) red[t >> 5] = ss;
    __syncthreads();
    float inv = 1.f / fmaxf(sqrtf(red[0] + red[1] + red[2] + red[3]), 1e-12f);
#pragma unroll
    for (int j = 0; j < 4; j++) g_shat[i * D_ + t + j * 128] = v[j] * inv;
}

// ---------------------------------------------------------------------------
// K2: S = Shat @ Shat^T (tiny, fp32 exact)
// ---------------------------------------------------------------------------
__global__ void k_slot_S() {
    int i = blockIdx.x, j = threadIdx.x;
    const float4* a = (const float4*)(g_shat + i * D_);
    const float4* b = (const float4*)(g_shat + j * D_);
    float acc = 0.f;
#pragma unroll 8
    for (int d = 0; d < D_ / 4; d++) {
        float4 x = a[d], y = b[d];
        acc += x.x * y.x + x.y * y.y + x.z * y.z + x.w * y.w;
    }
    g_S[i * K_ + j] = acc;
}

// ---------------------------------------------------------------------------
// K3: dots key-part via wmma tf32. CTA: 128 keys x 64 slots, K=512, kc=32.
// Fuses key row norms. Epilogue transposes via smem + scales by kinv.
// ---------------------------------------------------------------------------
// smem layout in floats:
constexpr int SD_KINV = 0;                    // 128
constexpr int SD_CS   = 128;                  // 64 x 132
constexpr int SD_AS   = SD_CS + 64 * 132;     // 2 x 128 x 40   (8576)
constexpr int SD_BS   = SD_AS + 2 * 128 * 40; // 2 x 64 x 40    (18816)
constexpr int SD_TOT  = SD_BS + 2 * 64 * 40;  // 23936 floats = 95744 B

__global__ __launch_bounds__(256) void k_dots(const float* __restrict__ key,
                                              float* __restrict__ dout) {
    extern __shared__ float smf[];
    const int t = threadIdx.x, wid = t >> 5;
    const int b = blockIdx.y, n0blk = blockIdx.x * 128;
    const float* keyb = key + (long)b * N_ * D_;

    const int m0 = (wid >> 1) * 32;   // key offset of warp tile
    const int n0 = (wid & 1) * 32;    // slot offset of warp tile

    wmma::fragment<wmma::accumulator, 16, 16, 8, float> c[2][2];
#pragma unroll
    for (int i = 0; i < 2; i++)
#pragma unroll
        for (int j = 0; j < 2; j++) wmma::fill_fragment(c[i][j], 0.f);

    const int rA = t >> 3, fA = t & 7;     // A staging coords
    float ss[4] = {0.f, 0.f, 0.f, 0.f};    // norm partials for rows rA+32q

    for (int jc = 0; jc < 16; jc++) {
        const int buf = jc & 1;
        const int d0 = jc * 32;
        float* As = smf + SD_AS + buf * (128 * 40);
        float* Bs = smf + SD_BS + buf * (64 * 40);
        // stage A: key[128 x 32] (row-major, ld 40), accumulate norms
#pragma unroll
        for (int q = 0; q < 4; q++) {
            int r = rA + 32 * q;
            float4 v = *(const float4*)(keyb + (long)(n0blk + r) * D_ + d0 + fA * 4);
            ss[q] += v.x * v.x + v.y * v.y + v.z * v.z + v.w * v.w;
            float4 w = {to_tf32(v.x), to_tf32(v.y), to_tf32(v.z), to_tf32(v.w)};
            *(float4*)(As + r * 40 + fA * 4) = w;
        }
        // stage B: Shat[64 x 32] as Bs[slot][k] (ld 40)
#pragma unroll
        for (int q = 0; q < 2; q++) {
            int idx = t + 256 * q;
            int s = idx >> 3, f = idx & 7;
            float4 v = *(const float4*)(g_shat + s * D_ + d0 + f * 4);
            float4 w = {to_tf32(v.x), to_tf32(v.y), to_tf32(v.z), to_tf32(v.w)};
            *(float4*)(Bs + s * 40 + f * 4) = w;
        }
        __syncthreads();
#pragma unroll
        for (int kk = 0; kk < 4; kk++) {
            int k0 = kk * 8;
            wmma::fragment<wmma::matrix_a, 16, 16, 8, wmma::precision::tf32, wmma::row_major> a0, a1;
            wmma::fragment<wmma::matrix_b, 16, 16, 8, wmma::precision::tf32, wmma::col_major> b0, b1;
            wmma::load_matrix_sync(a0, As + (m0)      * 40 + k0, 40);
            wmma::load_matrix_sync(a1, As + (m0 + 16) * 40 + k0, 40);
            wmma::load_matrix_sync(b0, Bs + (n0)      * 40 + k0, 40);
            wmma::load_matrix_sync(b1, Bs + (n0 + 16) * 40 + k0, 40);
            wmma::mma_sync(c[0][0], a0, b0, c[0][0]);
            wmma::mma_sync(c[0][1], a0, b1, c[0][1]);
            wmma::mma_sync(c[1][0], a1, b0, c[1][0]);
            wmma::mma_sync(c[1][1], a1, b1, c[1][1]);
        }
        __syncthreads();
    }

    // finalize key inverse norms (8 threads share each row)
#pragma unroll
    for (int q = 0; q < 4; q++) {
#pragma unroll
        for (int o = 1; o < 8; o <<= 1) ss[q] += __shfl_xor_sync(0xffffffffu, ss[q], o);
    }
    if (fA == 0) {
#pragma unroll
        for (int q = 0; q < 4; q++)
            smf[SD_KINV + rA + 32 * q] = 1.f / fmaxf(sqrtf(ss[q]), 1e-12f);
    }

    // store C fragments to smem col-major: Cs[slot][key], ld 132
#pragma unroll
    for (int i = 0; i < 2; i++)
#pragma unroll
        for (int j = 0; j < 2; j++)
            wmma::store_matrix_sync(smf + SD_CS + (n0 + 16 * j) * 132 + (m0 + 16 * i),
                                    c[i][j], 132, wmma::mem_col_major);
    __syncthreads();

    // write dots key-part: thread -> slot s = t>>2, key group kg = t&3
    {
        int s = t >> 2, kg = t & 3;
        const float* src = smf + SD_CS + s * 132 + kg * 32;
        const float* kv  = smf + SD_KINV + kg * 32;
        float* dst = dout + DOTS_OFF + (long)b * K_ * C_ + (long)s * C_ + K_ + n0blk + kg * 32;
#pragma unroll
        for (int g = 0; g < 8; g++) {
            float4 w = {src[g * 4 + 0] * kv[g * 4 + 0], src[g * 4 + 1] * kv[g * 4 + 1],
                        src[g * 4 + 2] * kv[g * 4 + 2], src[g * 4 + 3] * kv[g * 4 + 3]};
            *(float4*)(dst + g * 4) = w;
        }
    }
}

// ---------------------------------------------------------------------------
// K4: row softmax with block-causal mask -> g_attn; slot-slot dots -> output.
// ---------------------------------------------------------------------------
__global__ __launch_bounds__(256) void k_softmax(float* __restrict__ dout) {
    int row  = (blockIdx.x * blockDim.x + threadIdx.x) >> 5;
    int lane = threadIdx.x & 31;
    int b = row >> 6, i = row & 63;

    float* drow = dout + DOTS_OFF + (long)b * K_ * C_ + (long)i * C_;

    float sv[2], kvv[32];
    float m = -1e30f;
#pragma unroll
    for (int r = 0; r < 2; r++) {
        int c = lane + r * 32;
        float s = g_S[i * K_ + c];
        sv[r] = s;
        drow[c] = s;
        if (c < i) m = fmaxf(m, s);
    }
#pragma unroll
    for (int r = 0; r < 32; r++) {
        float v = drow[K_ + lane + r * 32];
        kvv[r] = v;
        m = fmaxf(m, v);
    }
#pragma unroll
    for (int o = 16; o; o >>= 1) m = fmaxf(m, __shfl_xor_sync(0xffffffffu, m, o));

    float sum = 0.f, es[2], ek[32];
#pragma unroll
    for (int r = 0; r < 2; r++) {
        int c = lane + r * 32;
        float x = (c < i) ? __expf((sv[r] - m) * TEMP_INV) : 0.f;
        es[r] = x; sum += x;
    }
#pragma unroll
    for (int r = 0; r < 32; r++) {
        float x = __expf((kvv[r] - m) * TEMP_INV);
        ek[r] = x; sum += x;
    }
#pragma unroll
    for (int o = 16; o; o >>= 1) sum += __shfl_xor_sync(0xffffffffu, sum, o);

    float inv = 1.f / (sum * (1.f + 1e-7f));
    float* at = g_attn + (long)row * C_;
#pragma unroll
    for (int r = 0; r < 2; r++) at[lane + r * 32] = es[r] * inv;
#pragma unroll
    for (int r = 0; r < 32; r++) at[K_ + lane + r * 32] = ek[r] * inv;
}

// ---------------------------------------------------------------------------
// K5: out = attn_n @ [slots; key_b] via wmma tf32.
// CTA: 64 slots x 128 d-cols, K=C=1088 in 34 chunks of 32. Direct global store.
// ---------------------------------------------------------------------------
constexpr int SO_AS  = 0;                      // 2 x 64 x 40
constexpr int SO_BS  = SO_AS + 2 * 64 * 40;    // 2 x 32 x 132  (5120)
constexpr int SO_TOT = SO_BS + 2 * 32 * 132;   // 13568 floats = 54272 B

__global__ __launch_bounds__(256) void k_out(const float* __restrict__ slot,
                                             const float* __restrict__ key,
                                             float* __restrict__ dout) {
    extern __shared__ float smf[];
    const int t = threadIdx.x, wid = t >> 5;
    const int b = blockIdx.y, d0 = blockIdx.x * 128;
    const float* keyb  = key + (long)b * N_ * D_;
    const float* attnb = g_attn + (long)b * K_ * C_;

    const int m0 = (wid & 1) * 32;    // slot offset
    const int n0 = (wid >> 1) * 32;   // d offset

    wmma::fragment<wmma::accumulator, 16, 16, 8, float> c[2][2];
#pragma unroll
    for (int i = 0; i < 2; i++)
#pragma unroll
        for (int j = 0; j < 2; j++) wmma::fill_fragment(c[i][j], 0.f);

    for (int jc = 0; jc < 34; jc++) {
        const int buf = jc & 1;
        const int c0 = jc * 32;
        float* As = smf + SO_AS + buf * (64 * 40);
        float* Bs = smf + SO_BS + buf * (32 * 132);
        // stage A: attn[64 x 32] row-major ld 40
#pragma unroll
        for (int q = 0; q < 2; q++) {
            int idx = t + 256 * q;
            int r = idx >> 3, f = idx & 7;
            float4 v = *(const float4*)(attnb + (long)r * C_ + c0 + f * 4);
            float4 w = {to_tf32(v.x), to_tf32(v.y), to_tf32(v.z), to_tf32(v.w)};
            *(float4*)(As + r * 40 + f * 4) = w;
        }
        // stage B: V rows c0..c0+31 (slot rows then key rows), [c][d] ld 132
#pragma unroll
        for (int q = 0; q < 4; q++) {
            int idx = t + 256 * q;
            int r = idx >> 5, f = idx & 31;
            int cc = c0 + r;
            const float* src = (cc < K_) ? (slot + (long)cc * D_ + d0 + f * 4)
                                         : (keyb + (long)(cc - K_) * D_ + d0 + f * 4);
            float4 v = *(const float4*)src;
            float4 w = {to_tf32(v.x), to_tf32(v.y), to_tf32(v.z), to_tf32(v.w)};
            *(float4*)(Bs + r * 132 + f * 4) = w;
        }
        __syncthreads();
#pragma unroll
        for (int kk = 0; kk < 4; kk++) {
            int k0 = kk * 8;
            wmma::fragment<wmma::matrix_a, 16, 16, 8, wmma::precision::tf32, wmma::row_major> a0, a1;
            wmma::fragment<wmma::matrix_b, 16, 16, 8, wmma::precision::tf32, wmma::row_major> b0, b1;
            wmma::load_matrix_sync(a0, As + (m0)      * 40 + k0, 40);
            wmma::load_matrix_sync(a1, As + (m0 + 16) * 40 + k0, 40);
            wmma::load_matrix_sync(b0, Bs + k0 * 132 + n0,      132);
            wmma::load_matrix_sync(b1, Bs + k0 * 132 + n0 + 16, 132);
            wmma::mma_sync(c[0][0], a0, b0, c[0][0]);
            wmma::mma_sync(c[0][1], a0, b1, c[0][1]);
            wmma::mma_sync(c[1][0], a1, b0, c[1][0]);
            wmma::mma_sync(c[1][1], a1, b1, c[1][1]);
        }
        __syncthreads();
    }

    // direct global store: out[b][slot][d]
#pragma unroll
    for (int i = 0; i < 2; i++)
#pragma unroll
        for (int j = 0; j < 2; j++) {
            float* gp = dout + (long)b * K_ * D_ + (long)(m0 + 16 * i) * D_ + d0 + n0 + 16 * j;
            wmma::store_matrix_sync(gp, c[i][j], D_, wmma::mem_row_major);
        }
}

// ---------------------------------------------------------------------------
extern "C" void kernel_launch(void* const* d_in, const int* in_sizes, int n_in,
                              void* d_out, int out_size) {
    const float* key  = (const float*)d_in[0];
    const float* slot = (const float*)d_in[1];
    float* out = (float*)d_out;

    cudaFuncSetAttribute(k_dots, cudaFuncAttributeMaxDynamicSharedMemorySize, SD_TOT * 4);
    cudaFuncSetAttribute(k_out,  cudaFuncAttributeMaxDynamicSharedMemorySize, SO_TOT * 4);

    k_slot_norm<<<K_, 128>>>(slot);
    k_slot_S<<<K_, K_>>>();
    k_dots<<<dim3(N_ / 128, B_), 256, SD_TOT * 4>>>(key, out);
    k_softmax<<<(B_ * K_) / 8, 256>>>(out);
    k_out<<<dim3(D_ / 128, B_), 256, SO_TOT * 4>>>(slot, key, out);
}

// round 5
// speedup vs baseline: 1.5699x; 1.0799x over previous
#include <cuda_runtime.h>
#include <mma.h>
#include <cstdint>
#include <math.h>

using namespace nvcuda;

constexpr int B_ = 64;
constexpr int N_ = 1024;
constexpr int D_ = 512;
constexpr int K_ = 64;
constexpr int C_ = K_ + N_;                      // 1088
constexpr long OUT_ELEMS = (long)B_ * K_ * D_;
constexpr long DOTS_OFF  = OUT_ELEMS;

#define TEMP_INV (1.0f / 0.07f)

__device__ float g_shat[K_ * D_];
__device__ float g_S[K_ * K_];
__device__ float g_attn[(long)B_ * K_ * C_];

__device__ __forceinline__ float to_tf32(float x) {
    asm("cvt.rna.tf32.f32 %0, %1;" : "=f"(x) : "f"(x));
    return x;
}
__device__ __forceinline__ float4 to_tf32_4(float4 v) {
    return {to_tf32(v.x), to_tf32(v.y), to_tf32(v.z), to_tf32(v.w)};
}

// ---------------------------------------------------------------------------
// K1: normalize slot embeddings
// ---------------------------------------------------------------------------
__global__ void k_slot_norm(const float* __restrict__ slot) {
    int i = blockIdx.x, t = threadIdx.x;
    float v[4]; float ss = 0.f;
#pragma unroll
    for (int j = 0; j < 4; j++) { v[j] = slot[i * D_ + t + j * 128]; ss += v[j] * v[j]; }
#pragma unroll
    for (int o = 16; o; o >>= 1) ss += __shfl_xor_sync(0xffffffffu, ss, o);
    __shared__ float red[4];
    if ((t & 31) == 0) red[t >> 5] = ss;
    __syncthreads();
    float inv = 1.f / fmaxf(sqrtf(red[0] + red[1] + red[2] + red[3]), 1e-12f);
#pragma unroll
    for (int j = 0; j < 4; j++) g_shat[i * D_ + t + j * 128] = v[j] * inv;
}

// ---------------------------------------------------------------------------
// K2: S = Shat @ Shat^T (tiny, fp32 exact)
// ---------------------------------------------------------------------------
__global__ void k_slot_S() {
    int i = blockIdx.x, j = threadIdx.x;
    const float4* a = (const float4*)(g_shat + i * D_);
    const float4* b = (const float4*)(g_shat + j * D_);
    float acc = 0.f;
#pragma unroll 8
    for (int d = 0; d < D_ / 4; d++) {
        float4 x = a[d], y = b[d];
        acc += x.x * y.x + x.y * y.y + x.z * y.z + x.w * y.w;
    }
    g_S[i * K_ + j] = acc;
}

// ---------------------------------------------------------------------------
// K3: dots key-part via wmma tf32, software-pipelined staging.
// CTA: 128 keys x 64 slots, K=512 in 16 chunks of 32. Fuses key row norms.
// ---------------------------------------------------------------------------
constexpr int SD_KINV = 0;                    // 128
constexpr int SD_CS   = 128;                  // 64 x 132
constexpr int SD_AS   = SD_CS + 64 * 132;     // 2 x 128 x 40
constexpr int SD_BS   = SD_AS + 2 * 128 * 40; // 2 x 64 x 40
constexpr int SD_TOT  = SD_BS + 2 * 64 * 40;  // floats

__global__ __launch_bounds__(256) void k_dots(const float* __restrict__ key,
                                              float* __restrict__ dout) {
    extern __shared__ float smf[];
    const int t = threadIdx.x, wid = t >> 5;
    const int b = blockIdx.y, n0blk = blockIdx.x * 128;
    const float* keyb = key + (long)b * N_ * D_;

    const int m0 = (wid >> 1) * 32;   // key offset of warp tile
    const int n0 = (wid & 1) * 32;    // slot offset of warp tile

    wmma::fragment<wmma::accumulator, 16, 16, 8, float> c[2][2];
#pragma unroll
    for (int i = 0; i < 2; i++)
#pragma unroll
        for (int j = 0; j < 2; j++) wmma::fill_fragment(c[i][j], 0.f);

    const int rA = t >> 3, fA = t & 7;     // A staging coords
    const int sB = t >> 3;                 // B staging row (with +32 for q=1 via idx)
    float ss[4] = {0.f, 0.f, 0.f, 0.f};    // norm partials for rows rA+32q

    float4 pa[4], pb[2];                   // prefetch registers

    auto ldg_chunk = [&](int jc) {
        const int d0 = jc * 32;
#pragma unroll
        for (int q = 0; q < 4; q++) {
            int r = rA + 32 * q;
            float4 v = *(const float4*)(keyb + (long)(n0blk + r) * D_ + d0 + fA * 4);
            ss[q] += v.x * v.x + v.y * v.y + v.z * v.z + v.w * v.w;
            pa[q] = v;
        }
#pragma unroll
        for (int q = 0; q < 2; q++) {
            int idx = t + 256 * q;
            int s = idx >> 3, f = idx & 7;
            pb[q] = *(const float4*)(g_shat + s * D_ + d0 + f * 4);
        }
    };
    auto sts_chunk = [&](int buf) {
        float* As = smf + SD_AS + buf * (128 * 40);
        float* Bs = smf + SD_BS + buf * (64 * 40);
#pragma unroll
        for (int q = 0; q < 4; q++) {
            int r = rA + 32 * q;
            *(float4*)(As + r * 40 + fA * 4) = to_tf32_4(pa[q]);
        }
#pragma unroll
        for (int q = 0; q < 2; q++) {
            int idx = t + 256 * q;
            int s = idx >> 3, f = idx & 7;
            *(float4*)(Bs + s * 40 + f * 4) = to_tf32_4(pb[q]);
        }
    };

    ldg_chunk(0);
    sts_chunk(0);
    __syncthreads();

    for (int jc = 0; jc < 16; jc++) {
        const int buf = jc & 1;
        const bool more = (jc + 1 < 16);
        if (more) ldg_chunk(jc + 1);       // in flight under the mma below
        float* As = smf + SD_AS + buf * (128 * 40);
        float* Bs = smf + SD_BS + buf * (64 * 40);
#pragma unroll
        for (int kk = 0; kk < 4; kk++) {
            int k0 = kk * 8;
            wmma::fragment<wmma::matrix_a, 16, 16, 8, wmma::precision::tf32, wmma::row_major> a0, a1;
            wmma::fragment<wmma::matrix_b, 16, 16, 8, wmma::precision::tf32, wmma::col_major> b0, b1;
            wmma::load_matrix_sync(a0, As + (m0)      * 40 + k0, 40);
            wmma::load_matrix_sync(a1, As + (m0 + 16) * 40 + k0, 40);
            wmma::load_matrix_sync(b0, Bs + (n0)      * 40 + k0, 40);
            wmma::load_matrix_sync(b1, Bs + (n0 + 16) * 40 + k0, 40);
            wmma::mma_sync(c[0][0], a0, b0, c[0][0]);
            wmma::mma_sync(c[0][1], a0, b1, c[0][1]);
            wmma::mma_sync(c[1][0], a1, b0, c[1][0]);
            wmma::mma_sync(c[1][1], a1, b1, c[1][1]);
        }
        if (more) sts_chunk(buf ^ 1);      // other buffer: safe, fenced by last bar
        __syncthreads();
    }

    // finalize key inverse norms (8 threads share each row)
#pragma unroll
    for (int q = 0; q < 4; q++) {
#pragma unroll
        for (int o = 1; o < 8; o <<= 1) ss[q] += __shfl_xor_sync(0xffffffffu, ss[q], o);
    }
    if (fA == 0) {
#pragma unroll
        for (int q = 0; q < 4; q++)
            smf[SD_KINV + rA + 32 * q] = 1.f / fmaxf(sqrtf(ss[q]), 1e-12f);
    }

    // store C fragments to smem col-major: Cs[slot][key], ld 132
#pragma unroll
    for (int i = 0; i < 2; i++)
#pragma unroll
        for (int j = 0; j < 2; j++)
            wmma::store_matrix_sync(smf + SD_CS + (n0 + 16 * j) * 132 + (m0 + 16 * i),
                                    c[i][j], 132, wmma::mem_col_major);
    __syncthreads();

    // write dots key-part: thread -> slot s = t>>2, key group kg = t&3
    {
        int s = t >> 2, kg = t & 3;
        const float* src = smf + SD_CS + s * 132 + kg * 32;
        const float* kv  = smf + SD_KINV + kg * 32;
        float* dst = dout + DOTS_OFF + (long)b * K_ * C_ + (long)s * C_ + K_ + n0blk + kg * 32;
#pragma unroll
        for (int g = 0; g < 8; g++) {
            float4 w = {src[g * 4 + 0] * kv[g * 4 + 0], src[g * 4 + 1] * kv[g * 4 + 1],
                        src[g * 4 + 2] * kv[g * 4 + 2], src[g * 4 + 3] * kv[g * 4 + 3]};
            *(float4*)(dst + g * 4) = w;
        }
    }
}

// ---------------------------------------------------------------------------
// K4: row softmax with block-causal mask -> g_attn; slot-slot dots -> output.
// ---------------------------------------------------------------------------
__global__ __launch_bounds__(256) void k_softmax(float* __restrict__ dout) {
    int row  = (blockIdx.x * blockDim.x + threadIdx.x) >> 5;
    int lane = threadIdx.x & 31;
    int b = row >> 6, i = row & 63;

    float* drow = dout + DOTS_OFF + (long)b * K_ * C_ + (long)i * C_;

    float sv[2], kvv[32];
    float m = -1e30f;
#pragma unroll
    for (int r = 0; r < 2; r++) {
        int c = lane + r * 32;
        float s = g_S[i * K_ + c];
        sv[r] = s;
        drow[c] = s;
        if (c < i) m = fmaxf(m, s);
    }
#pragma unroll
    for (int r = 0; r < 32; r++) {
        float v = drow[K_ + lane + r * 32];
        kvv[r] = v;
        m = fmaxf(m, v);
    }
#pragma unroll
    for (int o = 16; o; o >>= 1) m = fmaxf(m, __shfl_xor_sync(0xffffffffu, m, o));

    float sum = 0.f, es[2], ek[32];
#pragma unroll
    for (int r = 0; r < 2; r++) {
        int c = lane + r * 32;
        float x = (c < i) ? __expf((sv[r] - m) * TEMP_INV) : 0.f;
        es[r] = x; sum += x;
    }
#pragma unroll
    for (int r = 0; r < 32; r++) {
        float x = __expf((kvv[r] - m) * TEMP_INV);
        ek[r] = x; sum += x;
    }
#pragma unroll
    for (int o = 16; o; o >>= 1) sum += __shfl_xor_sync(0xffffffffu, sum, o);

    float inv = 1.f / (sum * (1.f + 1e-7f));
    float* at = g_attn + (long)row * C_;
#pragma unroll
    for (int r = 0; r < 2; r++) at[lane + r * 32] = es[r] * inv;
#pragma unroll
    for (int r = 0; r < 32; r++) at[K_ + lane + r * 32] = ek[r] * inv;
}

// ---------------------------------------------------------------------------
// K5: out = attn_n @ [slots; key_b] via wmma tf32, software-pipelined.
// CTA: 64 slots x 128 d-cols, K=C=1088 in 34 chunks of 32. Direct global store.
// ---------------------------------------------------------------------------
constexpr int SO_AS  = 0;                      // 2 x 64 x 40
constexpr int SO_BS  = SO_AS + 2 * 64 * 40;    // 2 x 32 x 132
constexpr int SO_TOT = SO_BS + 2 * 32 * 132;   // floats

__global__ __launch_bounds__(256) void k_out(const float* __restrict__ slot,
                                             const float* __restrict__ key,
                                             float* __restrict__ dout) {
    extern __shared__ float smf[];
    const int t = threadIdx.x, wid = t >> 5;
    const int b = blockIdx.y, d0 = blockIdx.x * 128;
    const float* keyb  = key + (long)b * N_ * D_;
    const float* attnb = g_attn + (long)b * K_ * C_;

    const int m0 = (wid & 1) * 32;    // slot offset
    const int n0 = (wid >> 1) * 32;   // d offset

    wmma::fragment<wmma::accumulator, 16, 16, 8, float> c[2][2];
#pragma unroll
    for (int i = 0; i < 2; i++)
#pragma unroll
        for (int j = 0; j < 2; j++) wmma::fill_fragment(c[i][j], 0.f);

    float4 pa[2], pb[4];              // prefetch registers

    auto ldg_chunk = [&](int jc) {
        const int c0 = jc * 32;
#pragma unroll
        for (int q = 0; q < 2; q++) {
            int idx = t + 256 * q;
            int r = idx >> 3, f = idx & 7;
            pa[q] = *(const float4*)(attnb + (long)r * C_ + c0 + f * 4);
        }
#pragma unroll
        for (int q = 0; q < 4; q++) {
            int idx = t + 256 * q;
            int r = idx >> 5, f = idx & 31;
            int cc = c0 + r;
            const float* src = (cc < K_) ? (slot + (long)cc * D_ + d0 + f * 4)
                                         : (keyb + (long)(cc - K_) * D_ + d0 + f * 4);
            pb[q] = *(const float4*)src;
        }
    };
    auto sts_chunk = [&](int buf) {
        float* As = smf + SO_AS + buf * (64 * 40);
        float* Bs = smf + SO_BS + buf * (32 * 132);
#pragma unroll
        for (int q = 0; q < 2; q++) {
            int idx = t + 256 * q;
            int r = idx >> 3, f = idx & 7;
            *(float4*)(As + r * 40 + f * 4) = to_tf32_4(pa[q]);
        }
#pragma unroll
        for (int q = 0; q < 4; q++) {
            int idx = t + 256 * q;
            int r = idx >> 5, f = idx & 31;
            *(float4*)(Bs + r * 132 + f * 4) = to_tf32_4(pb[q]);
        }
    };

    ldg_chunk(0);
    sts_chunk(0);
    __syncthreads();

    for (int jc = 0; jc < 34; jc++) {
        const int buf = jc & 1;
        const bool more = (jc + 1 < 34);
        if (more) ldg_chunk(jc + 1);
        float* As = smf + SO_AS + buf * (64 * 40);
        float* Bs = smf + SO_BS + buf * (32 * 132);
#pragma unroll
        for (int kk = 0; kk < 4; kk++) {
            int k0 = kk * 8;
            wmma::fragment<wmma::matrix_a, 16, 16, 8, wmma::precision::tf32, wmma::row_major> a0, a1;
            wmma::fragment<wmma::matrix_b, 16, 16, 8, wmma::precision::tf32, wmma::row_major> b0, b1;
            wmma::load_matrix_sync(a0, As + (m0)      * 40 + k0, 40);
            wmma::load_matrix_sync(a1, As + (m0 + 16) * 40 + k0, 40);
            wmma::load_matrix_sync(b0, Bs + k0 * 132 + n0,      132);
            wmma::load_matrix_sync(b1, Bs + k0 * 132 + n0 + 16, 132);
            wmma::mma_sync(c[0][0], a0, b0, c[0][0]);
            wmma::mma_sync(c[0][1], a0, b1, c[0][1]);
            wmma::mma_sync(c[1][0], a1, b0, c[1][0]);
            wmma::mma_sync(c[1][1], a1, b1, c[1][1]);
        }
        if (more) sts_chunk(buf ^ 1);
        __syncthreads();
    }

    // direct global store: out[b][slot][d]
#pragma unroll
    for (int i = 0; i < 2; i++)
#pragma unroll
        for (int j = 0; j < 2; j++) {
            float* gp = dout + (long)b * K_ * D_ + (long)(m0 + 16 * i) * D_ + d0 + n0 + 16 * j;
            wmma::store_matrix_sync(gp, c[i][j], D_, wmma::mem_row_major);
        }
}

// ---------------------------------------------------------------------------
extern "C" void kernel_launch(void* const* d_in, const int* in_sizes, int n_in,
                              void* d_out, int out_size) {
    const float* key  = (const float*)d_in[0];
    const float* slot = (const float*)d_in[1];
    float* out = (float*)d_out;

    cudaFuncSetAttribute(k_dots, cudaFuncAttributeMaxDynamicSharedMemorySize, SD_TOT * 4);
    cudaFuncSetAttribute(k_out,  cudaFuncAttributeMaxDynamicSharedMemorySize, SO_TOT * 4);

    k_slot_norm<<<K_, 128>>>(slot);
    k_slot_S<<<K_, K_>>>();
    k_dots<<<dim3(N_ / 128, B_), 256, SD_TOT * 4>>>(key, out);
    k_softmax<<<(B_ * K_) / 8, 256>>>(out);
    k_out<<<dim3(D_ / 128, B_), 256, SO_TOT * 4>>>(slot, key, out);
}